// round 7
// baseline (speedup 1.0000x reference)
#include <cuda_runtime.h>
#include <stdint.h>

// Fixed shape family: B=1, H=8, D=64. N, E read from in_sizes at launch.
#define H 8
#define D 64
#define ROW_FLOATS (H * D)        // 512 floats = 2048 B per row
#define TILE_ROWS 16
#define TILE_BYTES (TILE_ROWS * ROW_FLOATS * 4)   // 32768
#define STAGES 4

// Scratch (allocation-free): N*H entries needed (800k typical). 4M headroom.
static __device__ float        g_attn[1 << 22];
static __device__ unsigned int g_m   [1 << 22];

__device__ __forceinline__ unsigned int f2key(unsigned int u) {
    return (u & 0x80000000u) ? ~u : (u | 0x80000000u);
}
__device__ __forceinline__ float key2f(unsigned int k) {
    unsigned int u = (k & 0x80000000u) ? (k ^ 0x80000000u) : ~k;
    return __uint_as_float(u);
}
__device__ __forceinline__ float fast_tanh(float x) {
    float e = __expf(2.0f * x);
    return 1.0f - __fdividef(2.0f, e + 1.0f);
}

// ── mbarrier helpers (inlined from ptx_helpers conventions) ──
__device__ __forceinline__ uint32_t smem_u32(const void* p) {
    return (uint32_t)__cvta_generic_to_shared(p);
}
__device__ __forceinline__ void mbar_init(uint32_t a, uint32_t cnt) {
    asm volatile("mbarrier.init.shared.b64 [%0], %1;" :: "r"(a), "r"(cnt) : "memory");
}
__device__ __forceinline__ void mbar_expect_tx(uint32_t a, uint32_t bytes) {
    asm volatile("mbarrier.arrive.expect_tx.shared.b64 _, [%0], %1;" :: "r"(a), "r"(bytes) : "memory");
}
__device__ __forceinline__ void mbar_arrive(uint32_t a) {
    asm volatile("mbarrier.arrive.shared.b64 _, [%0];" :: "r"(a) : "memory");
}
__device__ __forceinline__ void mbar_wait(uint32_t a, uint32_t ph) {
    asm volatile(
        "{\n\t.reg .pred P;\n\t"
        "WAIT_%=:\n\t"
        "mbarrier.try_wait.parity.acquire.cta.shared::cta.b64 P, [%0], %1, 0x989680;\n\t"
        "@P bra.uni DONE_%=;\n\t"
        "bra.uni WAIT_%=;\n\t"
        "DONE_%=:\n\t}"
        :: "r"(a), "r"(ph) : "memory");
}
__device__ __forceinline__ void bulk_g2s(uint32_t dst, const void* src, uint32_t bytes, uint32_t mbar) {
    asm volatile(
        "cp.async.bulk.shared::cluster.global.mbarrier::complete_tx::bytes [%0], [%1], %2, [%3];"
        :: "r"(dst), "l"(src), "r"(bytes), "r"(mbar) : "memory");
}

// ── K1 (TMA pipeline): 148 CTAs, 1/SM. Elected thread streams 32KB X tiles
// (16 rows) into a 4-stage SMEM ring via cp.async.bulk; 8 warps each reduce
// 2 rows/tile from SMEM with W-in-regs + shfl butterfly. Memory decoupled
// from compute -> DRAM pipe stays full.
// Element f = 4*lo + 128k + j -> h = 2k + (lane>>4), d = 4*lo + j.
__global__ void k1_tma(const float* __restrict__ X, const float* __restrict__ Wk,
                       int numTiles) {
    extern __shared__ char smem[];
    __shared__ __align__(8) unsigned long long barsto[2 * STAGES];
    const int tid = threadIdx.x, lane = tid & 31, wid = tid >> 5;
    const int lo = lane & 15, hi = lane >> 4;
    const uint32_t sbase = smem_u32(smem);
    const uint32_t bbase = smem_u32(barsto);
    #define FULLB(s)  (bbase + (uint32_t)(s) * 16u)
    #define EMPTYB(s) (bbase + (uint32_t)(s) * 16u + 8u)

    if (tid == 0) {
        #pragma unroll
        for (int s = 0; s < STAGES; s++) { mbar_init(FULLB(s), 1); mbar_init(EMPTYB(s), 8); }
    }
    __syncthreads();

    float w[4][4];
    #pragma unroll
    for (int k = 0; k < 4; k++)
        #pragma unroll
        for (int j = 0; j < 4; j++)
            w[k][j] = Wk[(4 * lo + j) * H + 2 * k + hi];

    const int t0 = blockIdx.x, G = gridDim.x;
    int cnt = (t0 < numTiles) ? (numTiles - t0 + G - 1) / G : 0;   // my tile count

    // Prologue: fill the ring.
    if (tid == 0) {
        int pre = cnt < STAGES ? cnt : STAGES;
        for (int j = 0; j < pre; j++) {
            mbar_expect_tx(FULLB(j), TILE_BYTES);
            bulk_g2s(sbase + j * TILE_BYTES,
                     X + (size_t)(t0 + (size_t)j * G) * TILE_ROWS * ROW_FLOATS,
                     TILE_BYTES, FULLB(j));
        }
    }

    for (int j = 0; j < cnt; j++) {
        int s = j & (STAGES - 1);
        int cph = (j / STAGES) & 1;
        mbar_wait(FULLB(s), cph);

        const float4* buf = (const float4*)(smem + (size_t)s * TILE_BYTES);
        long long n = (long long)(t0 + (long long)j * G) * TILE_ROWS + wid * 2;
        const float4* r0 = buf + (wid * 2) * (ROW_FLOATS / 4);
        float4 v0[4], v1[4];
        #pragma unroll
        for (int k = 0; k < 4; k++) { v0[k] = r0[lane + 32 * k]; v1[k] = r0[128 + lane + 32 * k]; }
        float s0[4], s1[4];
        #pragma unroll
        for (int k = 0; k < 4; k++) {
            s0[k] = v0[k].x * w[k][0] + v0[k].y * w[k][1] + v0[k].z * w[k][2] + v0[k].w * w[k][3];
            s1[k] = v1[k].x * w[k][0] + v1[k].y * w[k][1] + v1[k].z * w[k][2] + v1[k].w * w[k][3];
        }
        #pragma unroll
        for (int o = 8; o >= 1; o >>= 1) {
            #pragma unroll
            for (int k = 0; k < 4; k++) {
                s0[k] += __shfl_xor_sync(0xffffffffu, s0[k], o);
                s1[k] += __shfl_xor_sync(0xffffffffu, s1[k], o);
            }
        }
        if (lo == 0) {
            float* ar = g_attn + (size_t)n * H;
            #pragma unroll
            for (int k = 0; k < 4; k++) { ar[2 * k + hi] = fast_tanh(s0[k]); ar[H + 2 * k + hi] = fast_tanh(s1[k]); }
            if (hi == 0) {
                uint4 z = make_uint4(0u, 0u, 0u, 0u);
                uint4* mz = (uint4*)(g_m + (size_t)n * H);
                mz[0] = z; mz[1] = z; mz[2] = z; mz[3] = z;
            }
        }
        if (lane == 0) mbar_arrive(EMPTYB(s));

        // Producer: refill this stage with tile j+STAGES (after all 8 warps drain it).
        if (tid == 0 && j + STAGES < cnt) {
            int i = j + STAGES;
            int r = i / STAGES;                 // consumptions required = r
            mbar_wait(EMPTYB(s), (r + 1) & 1);  // completes after r-th consumption
            mbar_expect_tx(FULLB(s), TILE_BYTES);
            bulk_g2s(sbase + s * TILE_BYTES,
                     X + (size_t)(t0 + (size_t)i * G) * TILE_ROWS * ROW_FLOATS,
                     TILE_BYTES, FULLB(s));
        }
    }
    #undef FULLB
    #undef EMPTYB
}

// ── K1 tail: old LDG path for rows not covered by full tiles (start..N).
__global__ void k1_tail(const float4* __restrict__ X4, const float* __restrict__ Wk,
                        int start, int N) {
    int wid  = (blockIdx.x * blockDim.x + threadIdx.x) >> 5;
    int lane = threadIdx.x & 31;
    int lo = lane & 15, hi = lane >> 4;
    int n = start + wid;
    if (n >= N) return;
    float w[4][4];
    #pragma unroll
    for (int k = 0; k < 4; k++)
        #pragma unroll
        for (int j = 0; j < 4; j++)
            w[k][j] = Wk[(4 * lo + j) * H + 2 * k + hi];
    const float4* r0 = X4 + (size_t)n * (ROW_FLOATS / 4);
    float s0[4];
    #pragma unroll
    for (int k = 0; k < 4; k++) {
        float4 v = r0[lane + 32 * k];
        s0[k] = v.x * w[k][0] + v.y * w[k][1] + v.z * w[k][2] + v.w * w[k][3];
    }
    #pragma unroll
    for (int o = 8; o >= 1; o >>= 1)
        #pragma unroll
        for (int k = 0; k < 4; k++) s0[k] += __shfl_xor_sync(0xffffffffu, s0[k], o);
    if (lo == 0) {
        float* ar = g_attn + (size_t)n * H;
        #pragma unroll
        for (int k = 0; k < 4; k++) ar[2 * k + hi] = fast_tanh(s0[k]);
        if (hi == 0) {
            uint4 z = make_uint4(0u, 0u, 0u, 0u);
            uint4* mz = (uint4*)(g_m + (size_t)n * H);
            mz[0] = z; mz[1] = z;
        }
    }
}

// ── K2 (R6 best): 2 lanes per edge, half-row LDG.128 gathers (1 L1 wavefront
// per edge per table), racy read-filter before atomicMax.
__global__ void k2_max(const int* __restrict__ src, const int* __restrict__ tgt, int E) {
    int idx  = blockIdx.x * blockDim.x + threadIdx.x;
    int e    = idx >> 1;
    int half = idx & 1;
    if (e >= E) return;
    int s = __ldg(src + e), t = __ldg(tgt + e);
    uint4 a = *(const uint4*)(g_attn + (size_t)s * H + half * 4);
    unsigned int* mp = g_m + (size_t)t * H + half * 4;
    uint4 cur = *(const uint4*)mp;
    unsigned int k0 = f2key(a.x), k1 = f2key(a.y), k2 = f2key(a.z), k3 = f2key(a.w);
    if (k0 > cur.x) atomicMax(mp + 0, k0);
    if (k1 > cur.y) atomicMax(mp + 1, k1);
    if (k2 > cur.z) atomicMax(mp + 2, k2);
    if (k3 > cur.w) atomicMax(mp + 3, k3);
}

// ── K3 (R6 best): 2 lanes per edge. out = exp(a_src - m_tgt) * drop.
// (Denominator segment_max(exp(e-m)) + 1e-9 == 1.0f exactly in fp32.)
__global__ void k3_out(const int* __restrict__ src, const int* __restrict__ tgt,
                       const float4* __restrict__ drop4, float4* __restrict__ out4, int E) {
    int idx  = blockIdx.x * blockDim.x + threadIdx.x;
    int e    = idx >> 1;
    int half = idx & 1;
    if (e >= E) return;
    int s = __ldg(src + e), t = __ldg(tgt + e);
    float4 a = *(const float4*)(g_attn + (size_t)s * H + half * 4);
    uint4  m = *(const uint4*) (g_m    + (size_t)t * H + half * 4);
    float4 d = drop4[(size_t)e * 2 + half];
    float4 o;
    o.x = __expf(a.x - key2f(m.x)) * d.x;
    o.y = __expf(a.y - key2f(m.y)) * d.y;
    o.z = __expf(a.z - key2f(m.z)) * d.z;
    o.w = __expf(a.w - key2f(m.w)) * d.w;
    out4[(size_t)e * 2 + half] = o;
}

// Inputs (metadata order): 0:X(f32) 1:attn_kernel(f32 D*H) 2:targets(i32 E)
// 3:sources(i32 E) 4:degree(f32 N, unused) 5:drop_mask(f32 E*H) 6:N.
extern "C" void kernel_launch(void* const* d_in, const int* in_sizes, int n_in,
                              void* d_out, int out_size) {
    const float*  X    = (const float*)d_in[0];
    const float*  Wk   = (const float*)d_in[1];
    const int*    tgt  = (const int*)d_in[2];
    const int*    srcs = (const int*)d_in[3];
    const float4* drop = (const float4*)d_in[5];
    float4*       out  = (float4*)d_out;

    const int E = in_sizes[2];
    const int N = in_sizes[4];

    const int numTiles = N / TILE_ROWS;
    const int smemBytes = STAGES * TILE_BYTES;
    cudaFuncSetAttribute(k1_tma, cudaFuncAttributeMaxDynamicSharedMemorySize, smemBytes);
    k1_tma<<<148, 256, smemBytes>>>(X, Wk, numTiles);
    const int tail = N - numTiles * TILE_ROWS;
    if (tail > 0) {
        int tw = (tail * 32 + 255) / 256;
        k1_tail<<<tw, 256>>>((const float4*)X, Wk, numTiles * TILE_ROWS, N);
    }

    const int threads = E * 2;
    const int block = 256;
    const int grid  = (threads + block - 1) / block;
    k2_max<<<grid, block>>>(srcs, tgt, E);
    k3_out<<<grid, block>>>(srcs, tgt, drop, out, E);
}

// round 8
// speedup vs baseline: 1.0116x; 1.0116x over previous
#include <cuda_runtime.h>
#include <stdint.h>

// Fixed shape family: B=1, H=8, D=64. N, E read from in_sizes at launch.
#define H 8
#define D 64
#define ROW_F4 (H * D / 4)   // 128 float4 per row

// Scratch (allocation-free): N*H entries needed (800k typical). 4M headroom.
static __device__ float        g_attn[1 << 22];
static __device__ unsigned int g_m   [1 << 22];

__device__ __forceinline__ unsigned int f2key(unsigned int u) {
    return (u & 0x80000000u) ? ~u : (u | 0x80000000u);
}
__device__ __forceinline__ float key2f(unsigned int k) {
    unsigned int u = (k & 0x80000000u) ? (k ^ 0x80000000u) : ~k;
    return __uint_as_float(u);
}
__device__ __forceinline__ float fast_tanh(float x) {
    float e = __expf(2.0f * x);
    return 1.0f - __fdividef(2.0f, e + 1.0f);
}

// ── K1: warp per row-pair, grid-stride over pairs, DOUBLE-BUFFERED: the next
// pair's 8 LDG.128 are issued BEFORE the current pair's FFMA+SHFL reduction,
// so DRAM requests stay in flight through the compute phase. W in 16 regs.
// Element f = 4*lo + 128k + j -> h = 2k + (lane>>4), d = 4*lo + j.
__global__ void k1_attn(const float4* __restrict__ X4, const float* __restrict__ Wk,
                        int pairs, int totalWarps) {
    const int gwid = (blockIdx.x * blockDim.x + threadIdx.x) >> 5;
    const int lane = threadIdx.x & 31;
    const int lo = lane & 15, hi = lane >> 4;

    float w[4][4];
    #pragma unroll
    for (int k = 0; k < 4; k++)
        #pragma unroll
        for (int j = 0; j < 4; j++)
            w[k][j] = Wk[(4 * lo + j) * H + 2 * k + hi];

    int p = gwid;
    if (p >= pairs) return;

    float4 a[4], b[4];
    {
        const float4* r = X4 + (size_t)p * 2 * ROW_F4;
        #pragma unroll
        for (int k = 0; k < 4; k++) { a[k] = __ldcs(r + lane + 32 * k); b[k] = __ldcs(r + 128 + lane + 32 * k); }
    }

    while (true) {
        const int pn = p + totalWarps;
        const bool more = pn < pairs;
        float4 na[4], nb[4];
        if (more) {                      // prefetch next pair BEFORE reducing
            const float4* r = X4 + (size_t)pn * 2 * ROW_F4;
            #pragma unroll
            for (int k = 0; k < 4; k++) { na[k] = __ldcs(r + lane + 32 * k); nb[k] = __ldcs(r + 128 + lane + 32 * k); }
        }

        float s0[4], s1[4];
        #pragma unroll
        for (int k = 0; k < 4; k++) {
            s0[k] = a[k].x * w[k][0] + a[k].y * w[k][1] + a[k].z * w[k][2] + a[k].w * w[k][3];
            s1[k] = b[k].x * w[k][0] + b[k].y * w[k][1] + b[k].z * w[k][2] + b[k].w * w[k][3];
        }
        #pragma unroll
        for (int o = 8; o >= 1; o >>= 1) {
            #pragma unroll
            for (int k = 0; k < 4; k++) {
                s0[k] += __shfl_xor_sync(0xffffffffu, s0[k], o);
                s1[k] += __shfl_xor_sync(0xffffffffu, s1[k], o);
            }
        }
        if (lo == 0) {
            float* ar = g_attn + (size_t)p * 2 * H;
            #pragma unroll
            for (int k = 0; k < 4; k++) { ar[2 * k + hi] = fast_tanh(s0[k]); ar[H + 2 * k + hi] = fast_tanh(s1[k]); }
            if (hi == 0) {                     // re-init m keys every call
                uint4 z = make_uint4(0u, 0u, 0u, 0u);
                uint4* mz = (uint4*)(g_m + (size_t)p * 2 * H);
                mz[0] = z; mz[1] = z; mz[2] = z; mz[3] = z;
            }
        }
        if (!more) break;
        #pragma unroll
        for (int k = 0; k < 4; k++) { a[k] = na[k]; b[k] = nb[k]; }
        p = pn;
    }
}

// ── K1 tail: last row if N is odd (not the case for this shape, but safe).
__global__ void k1_tail(const float4* __restrict__ X4, const float* __restrict__ Wk, int n) {
    int lane = threadIdx.x & 31;
    int lo = lane & 15, hi = lane >> 4;
    float w[4][4];
    #pragma unroll
    for (int k = 0; k < 4; k++)
        #pragma unroll
        for (int j = 0; j < 4; j++)
            w[k][j] = Wk[(4 * lo + j) * H + 2 * k + hi];
    const float4* r = X4 + (size_t)n * ROW_F4;
    float s0[4];
    #pragma unroll
    for (int k = 0; k < 4; k++) {
        float4 v = r[lane + 32 * k];
        s0[k] = v.x * w[k][0] + v.y * w[k][1] + v.z * w[k][2] + v.w * w[k][3];
    }
    #pragma unroll
    for (int o = 8; o >= 1; o >>= 1)
        #pragma unroll
        for (int k = 0; k < 4; k++) s0[k] += __shfl_xor_sync(0xffffffffu, s0[k], o);
    if (lo == 0) {
        float* ar = g_attn + (size_t)n * H;
        #pragma unroll
        for (int k = 0; k < 4; k++) ar[2 * k + hi] = fast_tanh(s0[k]);
        if (hi == 0) {
            uint4 z = make_uint4(0u, 0u, 0u, 0u);
            uint4* mz = (uint4*)(g_m + (size_t)n * H);
            mz[0] = z; mz[1] = z;
        }
    }
}

// ── K2 (R6 best): 2 lanes per edge, half-row LDG.128 gathers (1 L1 wavefront
// per edge per table), racy read-filter before atomicMax (stale-low reads
// only cost an extra atomic, never correctness).
__global__ void k2_max(const int* __restrict__ src, const int* __restrict__ tgt, int E) {
    int idx  = blockIdx.x * blockDim.x + threadIdx.x;
    int e    = idx >> 1;
    int half = idx & 1;
    if (e >= E) return;
    int s = __ldg(src + e), t = __ldg(tgt + e);
    uint4 a = *(const uint4*)(g_attn + (size_t)s * H + half * 4);
    unsigned int* mp = g_m + (size_t)t * H + half * 4;
    uint4 cur = *(const uint4*)mp;
    unsigned int k0 = f2key(a.x), k1 = f2key(a.y), k2 = f2key(a.z), k3 = f2key(a.w);
    if (k0 > cur.x) atomicMax(mp + 0, k0);
    if (k1 > cur.y) atomicMax(mp + 1, k1);
    if (k2 > cur.z) atomicMax(mp + 2, k2);
    if (k3 > cur.w) atomicMax(mp + 3, k3);
}

// ── K3 (R6 best): 2 lanes per edge. out = exp(a_src - m_tgt) * drop.
// (Denominator segment_max(exp(e-m)) + 1e-9 == 1.0f exactly in fp32: every
// segment attains exp(0)=1 and 1e-9 underflows the ulp of 1.0.)
__global__ void k3_out(const int* __restrict__ src, const int* __restrict__ tgt,
                       const float4* __restrict__ drop4, float4* __restrict__ out4, int E) {
    int idx  = blockIdx.x * blockDim.x + threadIdx.x;
    int e    = idx >> 1;
    int half = idx & 1;
    if (e >= E) return;
    int s = __ldg(src + e), t = __ldg(tgt + e);
    float4 a = *(const float4*)(g_attn + (size_t)s * H + half * 4);
    uint4  m = *(const uint4*) (g_m    + (size_t)t * H + half * 4);
    float4 d = drop4[(size_t)e * 2 + half];
    float4 o;
    o.x = __expf(a.x - key2f(m.x)) * d.x;
    o.y = __expf(a.y - key2f(m.y)) * d.y;
    o.z = __expf(a.z - key2f(m.z)) * d.z;
    o.w = __expf(a.w - key2f(m.w)) * d.w;
    out4[(size_t)e * 2 + half] = o;
}

// Inputs (metadata order): 0:X(f32) 1:attn_kernel(f32 D*H) 2:targets(i32 E)
// 3:sources(i32 E) 4:degree(f32 N, unused) 5:drop_mask(f32 E*H) 6:N.
extern "C" void kernel_launch(void* const* d_in, const int* in_sizes, int n_in,
                              void* d_out, int out_size) {
    const float4* X4   = (const float4*)d_in[0];
    const float*  Wk   = (const float*)d_in[1];
    const int*    tgt  = (const int*)d_in[2];
    const int*    srcs = (const int*)d_in[3];
    const float4* drop = (const float4*)d_in[5];
    float4*       out  = (float4*)d_out;

    const int E = in_sizes[2];
    const int N = in_sizes[4];

    const int pairs = N / 2;
    const int k1_blocks = 592;                         // ~16 warps/SM resident at ~100 regs
    k1_attn<<<k1_blocks, 256>>>(X4, Wk, pairs, k1_blocks * (256 / 32));
    if (N & 1) k1_tail<<<1, 32>>>(X4, Wk, N - 1);

    const int threads = E * 2;
    const int block = 256;
    const int grid  = (threads + block - 1) / block;
    k2_max<<<grid, block>>>(srcs, tgt, E);
    k3_out<<<grid, block>>>(srcs, tgt, drop, out, E);
}

// round 9
// speedup vs baseline: 1.0623x; 1.0501x over previous
#include <cuda_runtime.h>
#include <stdint.h>

// Fixed shape family: B=1, H=8, D=64. N, E read from in_sizes at launch.
#define H 8
#define D 64

// Scratch (allocation-free). All table values are POSITIVE floats, so raw
// IEEE bits order identically to unsigned ints -> no key transform anywhere.
static __device__ float        g_ea[1 << 22];  // exp(tanh(attn[n,h])) in (0.367, 2.72)
static __device__ unsigned int g_m [1 << 22];  // running max of ea bits; then 1/max after k_recip

// Fast tanh via hardware exp (MUFU.EX2): rel err ~1e-7.
__device__ __forceinline__ float fast_tanh(float x) {
    float e = __expf(2.0f * x);
    return 1.0f - __fdividef(2.0f, e + 1.0f);
}

// ── K1 (R6-exact structure — the proven 39.7us config; 3 structural
// alternatives all regressed): warp per 2 adjacent rows, 8 independent
// LDG.128/lane in flight, W in 16 regs, streaming X loads. Now stores
// ea = exp(tanh(.)) (max commutes with monotone exp).
// Element f = 4*lo + 128k + j -> h = 2k + (lane>>4), d = 4*lo + j.
__global__ void k1_attn(const float4* __restrict__ X4, const float* __restrict__ Wk,
                        int N, int totalWarps) {
    int wid  = (blockIdx.x * blockDim.x + threadIdx.x) >> 5;
    int lane = threadIdx.x & 31;
    int lo = lane & 15, hi = lane >> 4;

    float w[4][4];
    #pragma unroll
    for (int k = 0; k < 4; k++)
        #pragma unroll
        for (int j = 0; j < 4; j++)
            w[k][j] = Wk[(4 * lo + j) * H + 2 * k + hi];

    for (int n = wid * 2; n < N; n += totalWarps * 2) {
        const float4* r0 = X4 + (size_t)n * (H * D / 4);
        bool two = (n + 1 < N);
        float4 v0[4], v1[4];
        #pragma unroll
        for (int k = 0; k < 4; k++) v0[k] = __ldcs(r0 + lane + 32 * k);
        if (two) {
            #pragma unroll
            for (int k = 0; k < 4; k++) v1[k] = __ldcs(r0 + 128 + lane + 32 * k);
        }
        float s0[4], s1[4];
        #pragma unroll
        for (int k = 0; k < 4; k++) {
            s0[k] = v0[k].x * w[k][0] + v0[k].y * w[k][1] + v0[k].z * w[k][2] + v0[k].w * w[k][3];
            s1[k] = two ? (v1[k].x * w[k][0] + v1[k].y * w[k][1] + v1[k].z * w[k][2] + v1[k].w * w[k][3]) : 0.0f;
        }
        #pragma unroll
        for (int o = 8; o >= 1; o >>= 1) {
            #pragma unroll
            for (int k = 0; k < 4; k++) {
                s0[k] += __shfl_xor_sync(0xffffffffu, s0[k], o);
                s1[k] += __shfl_xor_sync(0xffffffffu, s1[k], o);
            }
        }
        if (lo == 0) {
            float* ar = g_ea + (size_t)n * H;
            #pragma unroll
            for (int k = 0; k < 4; k++) ar[2 * k + hi] = __expf(fast_tanh(s0[k]));
            if (two) {
                #pragma unroll
                for (int k = 0; k < 4; k++) ar[H + 2 * k + hi] = __expf(fast_tanh(s1[k]));
            }
            if (hi == 0) {                     // re-init m to 0 (< any positive-float bits)
                uint4 z = make_uint4(0u, 0u, 0u, 0u);
                uint4* mz = (uint4*)(g_m + (size_t)n * H);
                mz[0] = z; mz[1] = z;
                if (two) { mz[2] = z; mz[3] = z; }
            }
        }
    }
}

// ── K2: 2 lanes per edge, half-row LDG.128 gathers (1 L1 wavefront per edge
// per table). Positive-float bits compare as uints -> atomicMax on raw bits,
// no transform. Racy read-filter before atomicMax (stale-low reads only cost
// an extra atomic, never correctness).
__global__ void k2_max(const int* __restrict__ src, const int* __restrict__ tgt, int E) {
    int idx  = blockIdx.x * blockDim.x + threadIdx.x;
    int e    = idx >> 1;
    int half = idx & 1;
    if (e >= E) return;
    int s = __ldg(src + e), t = __ldg(tgt + e);
    uint4 a = *(const uint4*)(g_ea + (size_t)s * H + half * 4);
    unsigned int* mp = g_m + (size_t)t * H + half * 4;
    uint4 cur = *(const uint4*)mp;
    if (a.x > cur.x) atomicMax(mp + 0, a.x);
    if (a.y > cur.y) atomicMax(mp + 1, a.y);
    if (a.z > cur.z) atomicMax(mp + 2, a.z);
    if (a.w > cur.w) atomicMax(mp + 3, a.w);
}

// ── K2.5: per-NODE (not per-edge!) reciprocal of the max table, in place.
// 0.8M values, float4-vectorized: ~2us. Untargeted rows hold 1/0=inf (never
// gathered by K3). Moves ALL division/exp work out of the 3.2M-edge pass.
__global__ void k_recip(int NH4) {
    int i = blockIdx.x * blockDim.x + threadIdx.x;
    if (i >= NH4) return;
    float4* p = (float4*)g_m + i;
    float4 v = *p;
    v.x = __fdividef(1.0f, v.x);
    v.y = __fdividef(1.0f, v.y);
    v.z = __fdividef(1.0f, v.z);
    v.w = __fdividef(1.0f, v.w);
    *p = v;
}

// ── K3: 2 lanes per edge. out = ea[src] * rm[tgt] * drop — pure FMUL, no
// MUFU, no key transform. (Reference denominator segment_max(exp(e-m))+1e-9
// == 1.0f exactly in fp32, so it's a no-op.) drop/out are single-use streams:
// .cs hints keep L2 for the gather tables.
__global__ void k3_out(const int* __restrict__ src, const int* __restrict__ tgt,
                       const float4* __restrict__ drop4, float4* __restrict__ out4, int E) {
    int idx  = blockIdx.x * blockDim.x + threadIdx.x;
    int e    = idx >> 1;
    int half = idx & 1;
    if (e >= E) return;
    int s = __ldg(src + e), t = __ldg(tgt + e);
    float4 a = *(const float4*)(g_ea + (size_t)s * H + half * 4);
    float4 r = *(const float4*)((const float*)g_m + (size_t)t * H + half * 4);
    float4 d = __ldcs(drop4 + (size_t)e * 2 + half);
    float4 o;
    o.x = a.x * r.x * d.x;
    o.y = a.y * r.y * d.y;
    o.z = a.z * r.z * d.z;
    o.w = a.w * r.w * d.w;
    __stcs(out4 + (size_t)e * 2 + half, o);
}

// Inputs (metadata order): 0:X(f32) 1:attn_kernel(f32 D*H) 2:targets(i32 E)
// 3:sources(i32 E) 4:degree(f32 N, unused) 5:drop_mask(f32 E*H) 6:N.
extern "C" void kernel_launch(void* const* d_in, const int* in_sizes, int n_in,
                              void* d_out, int out_size) {
    const float4* X4   = (const float4*)d_in[0];
    const float*  Wk   = (const float*)d_in[1];
    const int*    tgt  = (const int*)d_in[2];
    const int*    srcs = (const int*)d_in[3];
    const float4* drop = (const float4*)d_in[5];
    float4*       out  = (float4*)d_out;

    const int E = in_sizes[2];
    const int N = in_sizes[4];

    const int k1_blocks = 1184;
    k1_attn<<<k1_blocks, 256>>>(X4, Wk, N, k1_blocks * (256 / 32));

    const int threads = E * 2;
    const int block = 256;
    const int grid  = (threads + block - 1) / block;
    k2_max<<<grid, block>>>(srcs, tgt, E);

    const int NH4 = (N * H) / 4;
    k_recip<<<(NH4 + 255) / 256, 256>>>(NH4);

    k3_out<<<grid, block>>>(srcs, tgt, drop, out, E);
}

// round 10
// speedup vs baseline: 1.0653x; 1.0029x over previous
#include <cuda_runtime.h>
#include <stdint.h>

// Fixed shape family: B=1, H=8, D=64. N, E read from in_sizes at launch.
#define H 8
#define D 64

// Scratch (allocation-free). All table values are POSITIVE floats, so raw
// IEEE bits order identically to unsigned ints -> no key transform anywhere.
static __device__ float        g_ea[1 << 22];  // exp(tanh(attn[n,h])) in (0.367, 2.72)
static __device__ unsigned int g_m [1 << 22];  // running max of ea bits; then 1/max after k_recip

// Fast tanh via hardware exp (MUFU.EX2): rel err ~1e-7.
__device__ __forceinline__ float fast_tanh(float x) {
    float e = __expf(2.0f * x);
    return 1.0f - __fdividef(2.0f, e + 1.0f);
}

// ── K1 (R6-proven structure; block shrunk 256->128 for 9 blocks/SM instead
// of 4 at 56 regs -> 36 resident warps vs 32, more loads in flight at the
// same per-warp MLP=8): warp per 2 adjacent rows, 8 independent LDG.128/lane,
// W in 16 regs, streaming X loads. Stores ea = exp(tanh(.)).
// Element f = 4*lo + 128k + j -> h = 2k + (lane>>4), d = 4*lo + j.
__global__ void k1_attn(const float4* __restrict__ X4, const float* __restrict__ Wk,
                        int N, int totalWarps) {
    int wid  = (blockIdx.x * blockDim.x + threadIdx.x) >> 5;
    int lane = threadIdx.x & 31;
    int lo = lane & 15, hi = lane >> 4;

    float w[4][4];
    #pragma unroll
    for (int k = 0; k < 4; k++)
        #pragma unroll
        for (int j = 0; j < 4; j++)
            w[k][j] = Wk[(4 * lo + j) * H + 2 * k + hi];

    for (int n = wid * 2; n < N; n += totalWarps * 2) {
        const float4* r0 = X4 + (size_t)n * (H * D / 4);
        bool two = (n + 1 < N);
        float4 v0[4], v1[4];
        #pragma unroll
        for (int k = 0; k < 4; k++) v0[k] = __ldcs(r0 + lane + 32 * k);
        if (two) {
            #pragma unroll
            for (int k = 0; k < 4; k++) v1[k] = __ldcs(r0 + 128 + lane + 32 * k);
        }
        float s0[4], s1[4];
        #pragma unroll
        for (int k = 0; k < 4; k++) {
            s0[k] = v0[k].x * w[k][0] + v0[k].y * w[k][1] + v0[k].z * w[k][2] + v0[k].w * w[k][3];
            s1[k] = two ? (v1[k].x * w[k][0] + v1[k].y * w[k][1] + v1[k].z * w[k][2] + v1[k].w * w[k][3]) : 0.0f;
        }
        #pragma unroll
        for (int o = 8; o >= 1; o >>= 1) {
            #pragma unroll
            for (int k = 0; k < 4; k++) {
                s0[k] += __shfl_xor_sync(0xffffffffu, s0[k], o);
                s1[k] += __shfl_xor_sync(0xffffffffu, s1[k], o);
            }
        }
        if (lo == 0) {
            float* ar = g_ea + (size_t)n * H;
            #pragma unroll
            for (int k = 0; k < 4; k++) ar[2 * k + hi] = __expf(fast_tanh(s0[k]));
            if (two) {
                #pragma unroll
                for (int k = 0; k < 4; k++) ar[H + 2 * k + hi] = __expf(fast_tanh(s1[k]));
            }
            if (hi == 0) {                     // re-init m to 0 (< any positive-float bits)
                uint4 z = make_uint4(0u, 0u, 0u, 0u);
                uint4* mz = (uint4*)(g_m + (size_t)n * H);
                mz[0] = z; mz[1] = z;
                if (two) { mz[2] = z; mz[3] = z; }
            }
        }
    }
}

// ── K2 (R9-proven): 2 lanes per edge, half-row LDG.128 gathers (1 L1
// wavefront per edge per table), atomicMax on raw positive-float bits,
// racy read-filter (stale-low reads only cost an extra atomic).
__global__ void k2_max(const int* __restrict__ src, const int* __restrict__ tgt, int E) {
    int idx  = blockIdx.x * blockDim.x + threadIdx.x;
    int e    = idx >> 1;
    int half = idx & 1;
    if (e >= E) return;
    int s = __ldg(src + e), t = __ldg(tgt + e);
    uint4 a = *(const uint4*)(g_ea + (size_t)s * H + half * 4);
    unsigned int* mp = g_m + (size_t)t * H + half * 4;
    uint4 cur = *(const uint4*)mp;
    if (a.x > cur.x) atomicMax(mp + 0, a.x);
    if (a.y > cur.y) atomicMax(mp + 1, a.y);
    if (a.z > cur.z) atomicMax(mp + 2, a.z);
    if (a.w > cur.w) atomicMax(mp + 3, a.w);
}

// ── K2.5: per-NODE reciprocal of the max table in place (0.8M values, ~2us).
// Untargeted rows hold 1/0=inf (never gathered by K3).
__global__ void k_recip(int NH4) {
    int i = blockIdx.x * blockDim.x + threadIdx.x;
    if (i >= NH4) return;
    float4* p = (float4*)g_m + i;
    float4 v = *p;
    v.x = __fdividef(1.0f, v.x);
    v.y = __fdividef(1.0f, v.y);
    v.z = __fdividef(1.0f, v.z);
    v.w = __fdividef(1.0f, v.w);
    *p = v;
}

// ── K3: 2 lanes per edge, ILP=2 — each thread services its (edge,half) slot
// for edge e AND edge e+E/2: twice the independent gather chains per thread,
// identical wavefront structure (half-row LDG.128 gathers, contiguous 512B
// drop/out segments per warp-half). out = ea[src]*rm[tgt]*drop, pure FMUL.
// (Reference denominator segment_max(exp(e-m))+1e-9 == 1.0f exactly in fp32.)
__global__ void k3_out(const int* __restrict__ src, const int* __restrict__ tgt,
                       const float4* __restrict__ drop4, float4* __restrict__ out4,
                       int Ehalf) {
    int idx  = blockIdx.x * blockDim.x + threadIdx.x;
    int e0   = idx >> 1;
    int half = idx & 1;
    if (e0 >= Ehalf) return;
    int e1 = e0 + Ehalf;
    int s0 = __ldg(src + e0), t0 = __ldg(tgt + e0);
    int s1 = __ldg(src + e1), t1 = __ldg(tgt + e1);
    float4 a0 = *(const float4*)(g_ea + (size_t)s0 * H + half * 4);
    float4 a1 = *(const float4*)(g_ea + (size_t)s1 * H + half * 4);
    float4 r0 = *(const float4*)((const float*)g_m + (size_t)t0 * H + half * 4);
    float4 r1 = *(const float4*)((const float*)g_m + (size_t)t1 * H + half * 4);
    float4 d0 = __ldcs(drop4 + (size_t)e0 * 2 + half);
    float4 d1 = __ldcs(drop4 + (size_t)e1 * 2 + half);
    float4 o0, o1;
    o0.x = a0.x * r0.x * d0.x;  o0.y = a0.y * r0.y * d0.y;
    o0.z = a0.z * r0.z * d0.z;  o0.w = a0.w * r0.w * d0.w;
    o1.x = a1.x * r1.x * d1.x;  o1.y = a1.y * r1.y * d1.y;
    o1.z = a1.z * r1.z * d1.z;  o1.w = a1.w * r1.w * d1.w;
    __stcs(out4 + (size_t)e0 * 2 + half, o0);
    __stcs(out4 + (size_t)e1 * 2 + half, o1);
}

// K3 tail for odd E (not hit in this shape family, kept for safety).
__global__ void k3_tail(const int* __restrict__ src, const int* __restrict__ tgt,
                        const float4* __restrict__ drop4, float4* __restrict__ out4,
                        int eStart, int E) {
    int idx  = blockIdx.x * blockDim.x + threadIdx.x;
    int e    = eStart + (idx >> 1);
    int half = idx & 1;
    if (e >= E) return;
    int s = __ldg(src + e), t = __ldg(tgt + e);
    float4 a = *(const float4*)(g_ea + (size_t)s * H + half * 4);
    float4 r = *(const float4*)((const float*)g_m + (size_t)t * H + half * 4);
    float4 d = __ldcs(drop4 + (size_t)e * 2 + half);
    float4 o;
    o.x = a.x * r.x * d.x;  o.y = a.y * r.y * d.y;
    o.z = a.z * r.z * d.z;  o.w = a.w * r.w * d.w;
    __stcs(out4 + (size_t)e * 2 + half, o);
}

// Inputs (metadata order): 0:X(f32) 1:attn_kernel(f32 D*H) 2:targets(i32 E)
// 3:sources(i32 E) 4:degree(f32 N, unused) 5:drop_mask(f32 E*H) 6:N.
extern "C" void kernel_launch(void* const* d_in, const int* in_sizes, int n_in,
                              void* d_out, int out_size) {
    const float4* X4   = (const float4*)d_in[0];
    const float*  Wk   = (const float*)d_in[1];
    const int*    tgt  = (const int*)d_in[2];
    const int*    srcs = (const int*)d_in[3];
    const float4* drop = (const float4*)d_in[5];
    float4*       out  = (float4*)d_out;

    const int E = in_sizes[2];
    const int N = in_sizes[4];

    // K1: block 128, 2368 blocks -> same 9472 total warps, higher residency.
    const int k1_blocks = 2368;
    k1_attn<<<k1_blocks, 128>>>(X4, Wk, N, k1_blocks * (128 / 32));

    const int block = 256;
    {   // K2: E*2 lane-slots
        const int threads = E * 2;
        k2_max<<<(threads + block - 1) / block, block>>>(srcs, tgt, E);
    }

    const int NH4 = (N * H) / 4;
    k_recip<<<(NH4 + 255) / 256, 256>>>(NH4);

    {   // K3: Ehalf*2 lane-slots, each thread does 2 edges
        const int Ehalf = E / 2;
        const int threads = Ehalf * 2;
        k3_out<<<(threads + block - 1) / block, block>>>(srcs, tgt, drop, out, Ehalf);
        if (E & 1)
            k3_tail<<<1, 2>>>(srcs, tgt, drop, out, Ehalf * 2, E);
    }
}

// round 11
// speedup vs baseline: 1.0819x; 1.0156x over previous
#include <cuda_runtime.h>
#include <stdint.h>

// Fixed shape family: B=1, H=8, D=64. N, E read from in_sizes at launch.
#define H 8
#define D 64

// Scratch (allocation-free). All table values are POSITIVE floats, so raw
// IEEE bits order identically to unsigned ints -> no key transform anywhere.
static __device__ float        g_ea[1 << 22];  // exp(tanh(attn[n,h])) in (0.367, 2.72)
static __device__ unsigned int g_m [1 << 22];  // running max of ea bits; then 1/max after k_recip

// Fast tanh via hardware exp (MUFU.EX2): rel err ~1e-7.
__device__ __forceinline__ float fast_tanh(float x) {
    float e = __expf(2.0f * x);
    return 1.0f - __fdividef(2.0f, e + 1.0f);
}

// ── K1 (R6-EXACT config, 39.7us @ 66% DRAM — 4 structural experiments all
// regressed; frozen): warp per 2 adjacent rows, 8 independent LDG.128/lane,
// W in 16 regs, streaming X loads, block 256 x 1184 blocks.
// Element f = 4*lo + 128k + j -> h = 2k + (lane>>4), d = 4*lo + j.
__global__ void k1_attn(const float4* __restrict__ X4, const float* __restrict__ Wk,
                        int N, int totalWarps) {
    int wid  = (blockIdx.x * blockDim.x + threadIdx.x) >> 5;
    int lane = threadIdx.x & 31;
    int lo = lane & 15, hi = lane >> 4;

    float w[4][4];
    #pragma unroll
    for (int k = 0; k < 4; k++)
        #pragma unroll
        for (int j = 0; j < 4; j++)
            w[k][j] = Wk[(4 * lo + j) * H + 2 * k + hi];

    for (int n = wid * 2; n < N; n += totalWarps * 2) {
        const float4* r0 = X4 + (size_t)n * (H * D / 4);
        bool two = (n + 1 < N);
        float4 v0[4], v1[4];
        #pragma unroll
        for (int k = 0; k < 4; k++) v0[k] = __ldcs(r0 + lane + 32 * k);
        if (two) {
            #pragma unroll
            for (int k = 0; k < 4; k++) v1[k] = __ldcs(r0 + 128 + lane + 32 * k);
        }
        float s0[4], s1[4];
        #pragma unroll
        for (int k = 0; k < 4; k++) {
            s0[k] = v0[k].x * w[k][0] + v0[k].y * w[k][1] + v0[k].z * w[k][2] + v0[k].w * w[k][3];
            s1[k] = two ? (v1[k].x * w[k][0] + v1[k].y * w[k][1] + v1[k].z * w[k][2] + v1[k].w * w[k][3]) : 0.0f;
        }
        #pragma unroll
        for (int o = 8; o >= 1; o >>= 1) {
            #pragma unroll
            for (int k = 0; k < 4; k++) {
                s0[k] += __shfl_xor_sync(0xffffffffu, s0[k], o);
                s1[k] += __shfl_xor_sync(0xffffffffu, s1[k], o);
            }
        }
        if (lo == 0) {
            float* ar = g_ea + (size_t)n * H;
            #pragma unroll
            for (int k = 0; k < 4; k++) ar[2 * k + hi] = __expf(fast_tanh(s0[k]));
            if (two) {
                #pragma unroll
                for (int k = 0; k < 4; k++) ar[H + 2 * k + hi] = __expf(fast_tanh(s1[k]));
            }
            if (hi == 0) {                     // re-init m to 0 (< any positive-float bits)
                uint4 z = make_uint4(0u, 0u, 0u, 0u);
                uint4* mz = (uint4*)(g_m + (size_t)n * H);
                mz[0] = z; mz[1] = z;
                if (two) { mz[2] = z; mz[3] = z; }
            }
        }
    }
}

// ── K2: 2 lanes per edge + ILP=2 (the pattern that gave K3 -9%): each thread
// services its (edge,half) slot for edge e AND e+Ehalf. Half-row LDG.128
// gathers (1 L1 wavefront per edge per table), atomicMax on raw positive-
// float bits, racy read-filter (stale-low reads only cost an extra atomic).
__global__ void k2_max(const int* __restrict__ src, const int* __restrict__ tgt, int Ehalf) {
    int idx  = blockIdx.x * blockDim.x + threadIdx.x;
    int e0   = idx >> 1;
    int half = idx & 1;
    if (e0 >= Ehalf) return;
    int e1 = e0 + Ehalf;
    int s0 = __ldg(src + e0), t0 = __ldg(tgt + e0);
    int s1 = __ldg(src + e1), t1 = __ldg(tgt + e1);
    uint4 a0 = *(const uint4*)(g_ea + (size_t)s0 * H + half * 4);
    uint4 a1 = *(const uint4*)(g_ea + (size_t)s1 * H + half * 4);
    unsigned int* mp0 = g_m + (size_t)t0 * H + half * 4;
    unsigned int* mp1 = g_m + (size_t)t1 * H + half * 4;
    uint4 c0 = *(const uint4*)mp0;
    uint4 c1 = *(const uint4*)mp1;
    if (a0.x > c0.x) atomicMax(mp0 + 0, a0.x);
    if (a0.y > c0.y) atomicMax(mp0 + 1, a0.y);
    if (a0.z > c0.z) atomicMax(mp0 + 2, a0.z);
    if (a0.w > c0.w) atomicMax(mp0 + 3, a0.w);
    if (a1.x > c1.x) atomicMax(mp1 + 0, a1.x);
    if (a1.y > c1.y) atomicMax(mp1 + 1, a1.y);
    if (a1.z > c1.z) atomicMax(mp1 + 2, a1.z);
    if (a1.w > c1.w) atomicMax(mp1 + 3, a1.w);
}

// K2 tail for odd E (not hit in this shape family).
__global__ void k2_tail(const int* __restrict__ src, const int* __restrict__ tgt,
                        int eStart, int E) {
    int idx  = blockIdx.x * blockDim.x + threadIdx.x;
    int e    = eStart + (idx >> 1);
    int half = idx & 1;
    if (e >= E) return;
    int s = __ldg(src + e), t = __ldg(tgt + e);
    uint4 a = *(const uint4*)(g_ea + (size_t)s * H + half * 4);
    unsigned int* mp = g_m + (size_t)t * H + half * 4;
    uint4 cur = *(const uint4*)mp;
    if (a.x > cur.x) atomicMax(mp + 0, a.x);
    if (a.y > cur.y) atomicMax(mp + 1, a.y);
    if (a.z > cur.z) atomicMax(mp + 2, a.z);
    if (a.w > cur.w) atomicMax(mp + 3, a.w);
}

// ── K2.5: per-NODE reciprocal of the max table in place (0.8M values, ~2us).
// Untargeted rows hold 1/0=inf (never gathered by K3).
__global__ void k_recip(int NH4) {
    int i = blockIdx.x * blockDim.x + threadIdx.x;
    if (i >= NH4) return;
    float4* p = (float4*)g_m + i;
    float4 v = *p;
    v.x = __fdividef(1.0f, v.x);
    v.y = __fdividef(1.0f, v.y);
    v.z = __fdividef(1.0f, v.z);
    v.w = __fdividef(1.0f, v.w);
    *p = v;
}

// ── K3 (R10-proven, 43.7us): 2 lanes per edge, ILP=2. out = ea[src]*rm[tgt]
// *drop, pure FMUL. (Reference denominator segment_max(exp(e-m))+1e-9 ==
// 1.0f exactly in fp32, so it's a no-op.)
__global__ void k3_out(const int* __restrict__ src, const int* __restrict__ tgt,
                       const float4* __restrict__ drop4, float4* __restrict__ out4,
                       int Ehalf) {
    int idx  = blockIdx.x * blockDim.x + threadIdx.x;
    int e0   = idx >> 1;
    int half = idx & 1;
    if (e0 >= Ehalf) return;
    int e1 = e0 + Ehalf;
    int s0 = __ldg(src + e0), t0 = __ldg(tgt + e0);
    int s1 = __ldg(src + e1), t1 = __ldg(tgt + e1);
    float4 a0 = *(const float4*)(g_ea + (size_t)s0 * H + half * 4);
    float4 a1 = *(const float4*)(g_ea + (size_t)s1 * H + half * 4);
    float4 r0 = *(const float4*)((const float*)g_m + (size_t)t0 * H + half * 4);
    float4 r1 = *(const float4*)((const float*)g_m + (size_t)t1 * H + half * 4);
    float4 d0 = __ldcs(drop4 + (size_t)e0 * 2 + half);
    float4 d1 = __ldcs(drop4 + (size_t)e1 * 2 + half);
    float4 o0, o1;
    o0.x = a0.x * r0.x * d0.x;  o0.y = a0.y * r0.y * d0.y;
    o0.z = a0.z * r0.z * d0.z;  o0.w = a0.w * r0.w * d0.w;
    o1.x = a1.x * r1.x * d1.x;  o1.y = a1.y * r1.y * d1.y;
    o1.z = a1.z * r1.z * d1.z;  o1.w = a1.w * r1.w * d1.w;
    __stcs(out4 + (size_t)e0 * 2 + half, o0);
    __stcs(out4 + (size_t)e1 * 2 + half, o1);
}

// K3 tail for odd E (not hit in this shape family).
__global__ void k3_tail(const int* __restrict__ src, const int* __restrict__ tgt,
                        const float4* __restrict__ drop4, float4* __restrict__ out4,
                        int eStart, int E) {
    int idx  = blockIdx.x * blockDim.x + threadIdx.x;
    int e    = eStart + (idx >> 1);
    int half = idx & 1;
    if (e >= E) return;
    int s = __ldg(src + e), t = __ldg(tgt + e);
    float4 a = *(const float4*)(g_ea + (size_t)s * H + half * 4);
    float4 r = *(const float4*)((const float*)g_m + (size_t)t * H + half * 4);
    float4 d = __ldcs(drop4 + (size_t)e * 2 + half);
    float4 o;
    o.x = a.x * r.x * d.x;  o.y = a.y * r.y * d.y;
    o.z = a.z * r.z * d.z;  o.w = a.w * r.w * d.w;
    __stcs(out4 + (size_t)e * 2 + half, o);
}

// Inputs (metadata order): 0:X(f32) 1:attn_kernel(f32 D*H) 2:targets(i32 E)
// 3:sources(i32 E) 4:degree(f32 N, unused) 5:drop_mask(f32 E*H) 6:N.
extern "C" void kernel_launch(void* const* d_in, const int* in_sizes, int n_in,
                              void* d_out, int out_size) {
    const float4* X4   = (const float4*)d_in[0];
    const float*  Wk   = (const float*)d_in[1];
    const int*    tgt  = (const int*)d_in[2];
    const int*    srcs = (const int*)d_in[3];
    const float4* drop = (const float4*)d_in[5];
    float4*       out  = (float4*)d_out;

    const int E = in_sizes[2];
    const int N = in_sizes[4];

    // K1: R6-exact launch (proven optimum).
    const int k1_blocks = 1184;
    k1_attn<<<k1_blocks, 256>>>(X4, Wk, N, k1_blocks * (256 / 32));

    const int block = 256;
    const int Ehalf = E / 2;
    {   // K2: Ehalf*2 lane-slots, each thread does 2 edges
        const int threads = Ehalf * 2;
        k2_max<<<(threads + block - 1) / block, block>>>(srcs, tgt, Ehalf);
        if (E & 1)
            k2_tail<<<1, 2>>>(srcs, tgt, Ehalf * 2, E);
    }

    const int NH4 = (N * H) / 4;
    k_recip<<<(NH4 + 255) / 256, 256>>>(NH4);

    {   // K3: Ehalf*2 lane-slots, each thread does 2 edges
        const int threads = Ehalf * 2;
        k3_out<<<(threads + block - 1) / block, block>>>(srcs, tgt, drop, out, Ehalf);
        if (E & 1)
            k3_tail<<<1, 2>>>(srcs, tgt, drop, out, Ehalf * 2, E);
    }
}